// round 10
// baseline (speedup 1.0000x reference)
#include <cuda_runtime.h>
#include <math.h>

// ContrastMemory: B=128, D=128, K+1=4097, N=100000, T=0.07, momentum=0.5
//
// Persistent kernel, GRID = 148*5 = 740 blocks co-resident (launch_bounds(256,5)).
// Phase 1: warp-granular work stealing (global ticket). Items: dot tiles
//          (32 k's of one sample, half-warp per k) and bank-copy chunks
//          (512 float4 of both banks), interleaved 3:1 by ticket id.
// Grid sync (counter), then Phase 2: reduce partial sums, scale outputs,
// momentum row updates. Counters self-reset for graph replay.
//
// Inputs: v1[B,D] f32, v2[B,D] f32, idx[B,K+1] i32, y[B] i32,
//         memory_v1[N,D] f32, memory_v2[N,D] f32
// Output: out_v1[B*(K+1)] | out_v2[B*(K+1)] | new_mem_v1[N*D] | new_mem_v2[N*D]

#define D_DIM  128
#define T_INV  (1.0f / 0.07f)
#define MOM    0.5f
#define OCC    5
#define GRID   (148 * OCC)   // 740
#define BLOCK  256
#define NWARP  8
#define CSZ    512           // float4 per copy item (x2 banks)

__device__ double       g_part[GRID * 2];
__device__ unsigned int g_ticket = 0;
__device__ unsigned int g_arrive = 0;
__device__ unsigned int g_done   = 0;

__device__ __forceinline__ float dot4(float4 p, float4 q) {
    return p.x * q.x + p.y * q.y + p.z * q.z + p.w * q.w;
}

__global__ __launch_bounds__(BLOCK, OCC)
void fused_kernel(const float* __restrict__ v1, const float* __restrict__ v2,
                  const int* __restrict__ idx, const int* __restrict__ y,
                  const float* __restrict__ m1, const float* __restrict__ m2,
                  float* __restrict__ out1, float* __restrict__ out2,
                  float* __restrict__ o_m1, float* __restrict__ o_m2,
                  int B, int K1, long n4,
                  int TPB, int NT, int NITEM, float factor_base)
{
    const int tid  = threadIdx.x;
    const int lane = tid & 31;
    const int warp = tid >> 5;
    const int jl   = lane & 15;   // chunk lane within half-warp
    const int grp  = lane >> 4;   // which k of the pair

    const float4* __restrict__ m1v = reinterpret_cast<const float4*>(m1);
    const float4* __restrict__ m2v = reinterpret_cast<const float4*>(m2);
    const float4* __restrict__ v1v = reinterpret_cast<const float4*>(v1);
    const float4* __restrict__ v2v = reinterpret_cast<const float4*>(v2);

    float sacc = 0.f;  // lanes 0,16: view1 partials; lanes 8,24: view2 partials

    // ---------------- Phase 1: ticket-stolen warp items ----------------
    for (;;) {
        unsigned int id;
        if (lane == 0) id = atomicAdd(&g_ticket, 1u);
        id = __shfl_sync(0xFFFFFFFFu, id, 0);
        if (id >= (unsigned int)NITEM) break;

        const int q   = id >> 2;
        const int rem = id & 3;

        if (rem == 3) {
            // ---- copy item q: CSZ float4 of both banks ----
            const float4* s1 = reinterpret_cast<const float4*>(m1);
            const float4* s2 = reinterpret_cast<const float4*>(m2);
            float4* d1 = reinterpret_cast<float4*>(o_m1);
            float4* d2 = reinterpret_cast<float4*>(o_m2);
            long base = (long)q * CSZ;
            long end  = base + CSZ; if (end > n4) end = n4;
            for (long i = base + lane; i < end; i += 32) {
                float4 a = __ldcg(&s1[i]);
                float4 b = __ldcg(&s2[i]);
                __stcs(&d1[i], a);
                __stcs(&d2[i], b);
            }
            continue;
        }

        // ---- dot item: 32 k's of sample b ----
        const int t = q * 3 + rem;
        if (t >= NT) continue;
        const int b     = t / TPB;
        const int chunk = t - b * TPB;
        const int kb    = chunk << 5;           // chunk * 32
        int cnt = K1 - kb; if (cnt > 32) cnt = 32;

        const int* __restrict__ idxb = idx + (long)b * K1;
        const int rv = (lane < cnt) ? idxb[kb + lane] : 0;

        // v chunks for this lane: jl and jl+16 (both views)
        const float4 A1a = v1v[b * 32 + jl];
        const float4 A1b = v1v[b * 32 + 16 + jl];
        const float4 A2a = v2v[b * 32 + jl];
        const float4 A2b = v2v[b * 32 + 16 + jl];

        float* __restrict__ ob1 = out1 + (long)b * K1 + kb;
        float* __restrict__ ob2 = out2 + (long)b * K1 + kb;

        #pragma unroll 2
        for (int j = 0; j < cnt; j += 2) {
            int ksel = j + grp;
            if (ksel > cnt - 1) ksel = cnt - 1;       // clamp for odd tail
            const int r = __shfl_sync(0xFFFFFFFFu, rv, ksel);

            const float4 xa = m1v[(long)r * 32 + jl];
            const float4 xb = m1v[(long)r * 32 + 16 + jl];
            const float4 ya = m2v[(long)r * 32 + jl];
            const float4 yb = m2v[(long)r * 32 + 16 + jl];

            // out_v1 uses m2-row vs v1; out_v2 uses m1-row vs v2
            float d1 = dot4(ya, A1a) + dot4(yb, A1b);
            float d2 = dot4(xa, A2a) + dot4(xb, A2b);

            // merged reduction over 16 lanes: after this, within each half-warp
            // lanes bit3=0 hold sum(d1), bit3=1 hold sum(d2)
            const float t1 = __shfl_xor_sync(0xFFFFFFFFu, d1, 8);
            const float t2 = __shfl_xor_sync(0xFFFFFFFFu, d2, 8);
            float a = (lane & 8) ? (d2 + t2) : (d1 + t1);
            a += __shfl_xor_sync(0xFFFFFFFFu, a, 4);
            a += __shfl_xor_sync(0xFFFFFFFFu, a, 2);
            a += __shfl_xor_sync(0xFFFFFFFFu, a, 1);

            const float e = __expf(a * T_INV);
            const bool ok1 = (j + 1 < cnt);
            if (lane == 0)        { ob1[j] = e;     sacc += e; }
            else if (lane == 8)   { ob2[j] = e;     sacc += e; }
            else if (lane == 16)  { if (ok1) { ob1[j + 1] = e; sacc += e; } }
            else if (lane == 24)  { if (ok1) { ob2[j + 1] = e; sacc += e; } }
        }
    }

    // -------- fold per-warp sums (view1: lanes 0,16; view2: lanes 8,24) --------
    __shared__ float sh1[NWARP], sh2[NWARP];
    {
        float s1 = (lane == 0 || lane == 16) ? sacc : 0.f;
        float s2 = (lane == 8 || lane == 24) ? sacc : 0.f;
        #pragma unroll
        for (int o = 16; o > 0; o >>= 1) {
            s1 += __shfl_xor_sync(0xFFFFFFFFu, s1, o);
            s2 += __shfl_xor_sync(0xFFFFFFFFu, s2, o);
        }
        if (lane == 0) { sh1[warp] = s1; sh2[warp] = s2; }
    }
    __syncthreads();

    // -------- block partials -> g_part, grid sync --------
    if (tid == 0) {
        double p1 = 0.0, p2 = 0.0;
        #pragma unroll
        for (int w = 0; w < NWARP; w++) { p1 += (double)sh1[w]; p2 += (double)sh2[w]; }
        g_part[2 * blockIdx.x]     = p1;
        g_part[2 * blockIdx.x + 1] = p2;
        __threadfence();
        atomicAdd(&g_arrive, 1u);
        while (*((volatile unsigned int*)&g_arrive) < GRID) { __nanosleep(64); }
        __threadfence();
    }
    __syncthreads();

    // ---------------- Phase 2: reduce, scale, update rows ----------------
    __shared__ double shd1[NWARP], shd2[NWARP];
    {
        double s1 = 0.0, s2 = 0.0;
        for (int i = tid; i < GRID; i += BLOCK) {
            s1 += g_part[2 * i];
            s2 += g_part[2 * i + 1];
        }
        #pragma unroll
        for (int o = 16; o > 0; o >>= 1) {
            s1 += __shfl_xor_sync(0xFFFFFFFFu, s1, o);
            s2 += __shfl_xor_sync(0xFFFFFFFFu, s2, o);
        }
        if (lane == 0) { shd1[warp] = s1; shd2[warp] = s2; }
    }
    __syncthreads();

    double sum1 = 0.0, sum2 = 0.0;
    #pragma unroll
    for (int w = 0; w < NWARP; w++) { sum1 += shd1[w]; sum2 += shd2[w]; }
    const float inv1 = (float)((double)factor_base / sum1);
    const float inv2 = (float)((double)factor_base / sum2);

    // scale both out arrays (B*K1 divisible by 4)
    {
        const long total4    = ((long)2 * B * K1) >> 2;
        const long boundary4 = ((long)B * K1) >> 2;
        float4* o = reinterpret_cast<float4*>(out1);
        for (long i = (long)blockIdx.x * BLOCK + tid; i < total4; i += (long)GRID * BLOCK) {
            float4 v = o[i];
            const float f = (i < boundary4) ? inv1 : inv2;
            v.x *= f; v.y *= f; v.z *= f; v.w *= f;
            o[i] = v;
        }
    }

    // momentum update + l2-normalize for the B touched rows (after copy)
    if (blockIdx.x < B && warp == 0) {
        const int bb  = blockIdx.x;
        const int row = y[bb];
        {
            float4 mv = m1v[(long)row * 32 + lane];
            float4 vv = reinterpret_cast<const float4*>(v1 + (long)bb * D_DIM)[lane];
            float4 u;
            u.x = MOM * mv.x + (1.f - MOM) * vv.x;
            u.y = MOM * mv.y + (1.f - MOM) * vv.y;
            u.z = MOM * mv.z + (1.f - MOM) * vv.z;
            u.w = MOM * mv.w + (1.f - MOM) * vv.w;
            float n = u.x * u.x + u.y * u.y + u.z * u.z + u.w * u.w;
            #pragma unroll
            for (int o = 16; o > 0; o >>= 1) n += __shfl_xor_sync(0xFFFFFFFFu, n, o);
            const float invn = 1.f / sqrtf(n);
            u.x *= invn; u.y *= invn; u.z *= invn; u.w *= invn;
            reinterpret_cast<float4*>(o_m1 + (long)row * D_DIM)[lane] = u;
        }
        {
            float4 mv = m2v[(long)row * 32 + lane];
            float4 vv = reinterpret_cast<const float4*>(v2 + (long)bb * D_DIM)[lane];
            float4 u;
            u.x = MOM * mv.x + (1.f - MOM) * vv.x;
            u.y = MOM * mv.y + (1.f - MOM) * vv.y;
            u.z = MOM * mv.z + (1.f - MOM) * vv.z;
            u.w = MOM * mv.w + (1.f - MOM) * vv.w;
            float n = u.x * u.x + u.y * u.y + u.z * u.z + u.w * u.w;
            #pragma unroll
            for (int o = 16; o > 0; o >>= 1) n += __shfl_xor_sync(0xFFFFFFFFu, n, o);
            const float invn = 1.f / sqrtf(n);
            u.x *= invn; u.y *= invn; u.z *= invn; u.w *= invn;
            reinterpret_cast<float4*>(o_m2 + (long)row * D_DIM)[lane] = u;
        }
    }

    // -------- counter reset (last finished block resets all) --------
    __syncthreads();
    if (tid == 0) {
        __threadfence();
        const unsigned int d = atomicAdd(&g_done, 1u);
        if (d == GRID - 1) {
            g_ticket = 0;
            g_arrive = 0;
            g_done   = 0;
            __threadfence();
        }
    }
}

extern "C" void kernel_launch(void* const* d_in, const int* in_sizes, int n_in,
                              void* d_out, int out_size)
{
    const float* v1  = (const float*)d_in[0];
    const float* v2  = (const float*)d_in[1];
    const int*   idx = (const int*)d_in[2];
    const int*   y   = (const int*)d_in[3];
    const float* m1  = (const float*)d_in[4];
    const float* m2  = (const float*)d_in[5];

    const int  B  = in_sizes[3];               // 128
    const int  K1 = in_sizes[2] / B;           // 4097
    const long ND = in_sizes[4];               // N * D
    const int  N  = (int)(ND / D_DIM);         // 100000

    float* out  = (float*)d_out;
    float* out1 = out;                         // [B*K1]
    float* out2 = out + (long)B * K1;          // [B*K1]
    float* o_m1 = out + 2L * B * K1;           // [N*D]
    float* o_m2 = o_m1 + ND;                   // [N*D]

    const long n4    = ND / 4;                           // 3,200,000
    const int  TPB   = (K1 + 31) / 32;                   // 129 tiles per sample
    const int  NT    = B * TPB;                          // 16512 dot items
    const int  NCOPY = (int)((n4 + CSZ - 1) / CSZ);      // 6250 copy items
    int groups = (NT + 2) / 3;
    if (NCOPY > groups) groups = NCOPY;
    const int  NITEM = groups * 4;                       // 25000 tickets

    const float factor_base = (float)((double)((long)B * K1) / (double)N);

    fused_kernel<<<GRID, BLOCK>>>(v1, v2, idx, y, m1, m2,
                                  out1, out2, o_m1, o_m2,
                                  B, K1, n4, TPB, NT, NITEM, factor_base);
}

// round 11
// speedup vs baseline: 1.4468x; 1.4468x over previous
#include <cuda_runtime.h>
#include <math.h>

// ContrastMemory: B=128, D=128, K+1=4097, N=100000, T=0.07, momentum=0.5
//
// Structure (reverted to measured-best R2 + fused tail):
//   1. init_sums  (zero the two accumulators)
//   2. main_kernel: 5120 HW-scheduled blocks; 4 of 5 do gather/dot/exp
//      (warp-per-k, 4-way unrolled), 1 of 5 streams the bank copy.
//   3. finish_kernel: scale out1/out2 by (B*K1)/(N*sum)  AND  momentum
//      row update (fused; replaces two separate launches).
//
// Inputs: v1[B,D] f32, v2[B,D] f32, idx[B,K+1] i32, y[B] i32,
//         memory_v1[N,D] f32, memory_v2[N,D] f32
// Output: out_v1[B*(K+1)] | out_v2[B*(K+1)] | new_mem_v1[N*D] | new_mem_v2[N*D]

#define D_DIM 128
#define T_INV (1.0f / 0.07f)
#define MOM 0.5f
#define SPLIT 32          // k-chunks per sample (dot blocks per b = SPLIT)
#define NWARP 8           // warps per block
#define COPY_GROUPS 1024  // copy blocks (1 per 4 dot blocks, interleaved)

__device__ double g_sum[2];

__global__ void init_sums_kernel() {
    g_sum[0] = 0.0;
    g_sum[1] = 0.0;
}

// Merged 2-value warp reduction: after this, lanes 0-15 all hold sum(d1),
// lanes 16-31 all hold sum(d2). 6 shuffles instead of 10.
__device__ __forceinline__ float reduce2(float d1, float d2, int lane) {
    float t = __shfl_xor_sync(0xFFFFFFFFu, d1, 16);
    float u = __shfl_xor_sync(0xFFFFFFFFu, d2, 16);
    float a = (lane < 16) ? (d1 + t) : (d2 + u);
    a += __shfl_xor_sync(0xFFFFFFFFu, a, 8);
    a += __shfl_xor_sync(0xFFFFFFFFu, a, 4);
    a += __shfl_xor_sync(0xFFFFFFFFu, a, 2);
    a += __shfl_xor_sync(0xFFFFFFFFu, a, 1);
    return a;
}

__device__ __forceinline__ float dot4(float4 p, float4 q) {
    return p.x * q.x + p.y * q.y + p.z * q.z + p.w * q.w;
}

// Fused kernel: 4 of every 5 blocks do gather/dot/exp, 1 of 5 streams the
// bank copy (DRAM-bound, overlaps with the L2-bound gather).
__global__ __launch_bounds__(256, 4)
void main_kernel(const float* __restrict__ v1, const float* __restrict__ v2,
                 const int* __restrict__ idx,
                 const float* __restrict__ m1, const float* __restrict__ m2,
                 float* __restrict__ out1, float* __restrict__ out2,
                 float* __restrict__ o_m1, float* __restrict__ o_m2,
                 int K1, long n4)
{
    const int gid   = blockIdx.x;
    const int group = gid / 5;
    const int rem   = gid - group * 5;

    if (rem == 4) {
        // ---- copy role: grid-stride float4 copy of both banks ----
        const float4* s1 = reinterpret_cast<const float4*>(m1);
        const float4* s2 = reinterpret_cast<const float4*>(m2);
        float4* d1 = reinterpret_cast<float4*>(o_m1);
        float4* d2 = reinterpret_cast<float4*>(o_m2);
        const long stride = (long)COPY_GROUPS * blockDim.x;
        for (long i = (long)group * blockDim.x + threadIdx.x; i < n4; i += stride) {
            float4 a = __ldcg(&s1[i]);
            float4 b = __ldcg(&s2[i]);
            __stcs(&d1[i], a);
            __stcs(&d2[i], b);
        }
        return;
    }

    // ---- dot role ----
    const int dot_id = group * 4 + rem;         // 0 .. B*SPLIT-1
    const int b      = dot_id >> 5;             // / SPLIT
    const int chunk  = dot_id & (SPLIT - 1);
    const int lane   = threadIdx.x & 31;
    const int warp   = threadIdx.x >> 5;

    const float4 a1 = reinterpret_cast<const float4*>(v1 + (long)b * D_DIM)[lane];
    const float4 a2 = reinterpret_cast<const float4*>(v2 + (long)b * D_DIM)[lane];

    const int* __restrict__ idxb = idx + (long)b * K1;
    float* __restrict__ ob1 = out1 + (long)b * K1;
    float* __restrict__ ob2 = out2 + (long)b * K1;

    const int widx = chunk * NWARP + warp;      // 0 .. 255
    const int W    = SPLIT * NWARP;             // 256

    float sacc = 0.f;   // lane0: e1-sum; lane16: e2-sum; others unused

    int k = widx;
    // 4-way unrolled main loop: 8 independent row loads in flight per warp.
    for (; k + 3 * W < K1; k += 4 * W) {
        const int r0 = idxb[k];
        const int r1 = idxb[k + W];
        const int r2 = idxb[k + 2 * W];
        const int r3 = idxb[k + 3 * W];

        const float4 x0 = reinterpret_cast<const float4*>(m1 + (long)r0 * D_DIM)[lane];
        const float4 y0 = reinterpret_cast<const float4*>(m2 + (long)r0 * D_DIM)[lane];
        const float4 x1 = reinterpret_cast<const float4*>(m1 + (long)r1 * D_DIM)[lane];
        const float4 y1 = reinterpret_cast<const float4*>(m2 + (long)r1 * D_DIM)[lane];
        const float4 x2 = reinterpret_cast<const float4*>(m1 + (long)r2 * D_DIM)[lane];
        const float4 y2 = reinterpret_cast<const float4*>(m2 + (long)r2 * D_DIM)[lane];
        const float4 x3 = reinterpret_cast<const float4*>(m1 + (long)r3 * D_DIM)[lane];
        const float4 y3 = reinterpret_cast<const float4*>(m2 + (long)r3 * D_DIM)[lane];

        // out_v1 uses w2 (m2) vs v1;  out_v2 uses w1 (m1) vs v2.
        float r1a = reduce2(dot4(y0, a1), dot4(x0, a2), lane);
        float r1b = reduce2(dot4(y1, a1), dot4(x1, a2), lane);
        float r1c = reduce2(dot4(y2, a1), dot4(x2, a2), lane);
        float r1d = reduce2(dot4(y3, a1), dot4(x3, a2), lane);

        float ea = __expf(r1a * T_INV);
        float eb = __expf(r1b * T_INV);
        float ec = __expf(r1c * T_INV);
        float ed = __expf(r1d * T_INV);

        if (lane == 0) {
            ob1[k] = ea; ob1[k + W] = eb; ob1[k + 2 * W] = ec; ob1[k + 3 * W] = ed;
            sacc += ea + eb + ec + ed;
        } else if (lane == 16) {
            ob2[k] = ea; ob2[k + W] = eb; ob2[k + 2 * W] = ec; ob2[k + 3 * W] = ed;
            sacc += ea + eb + ec + ed;
        }
    }
    // tail
    for (; k < K1; k += W) {
        const int r = idxb[k];
        const float4 x = reinterpret_cast<const float4*>(m1 + (long)r * D_DIM)[lane];
        const float4 y = reinterpret_cast<const float4*>(m2 + (long)r * D_DIM)[lane];
        float rr = reduce2(dot4(y, a1), dot4(x, a2), lane);
        float e  = __expf(rr * T_INV);
        if (lane == 0)       { ob1[k] = e; sacc += e; }
        else if (lane == 16) { ob2[k] = e; sacc += e; }
    }

    __shared__ float sh1[NWARP], sh2[NWARP];
    if (lane == 0)  sh1[warp] = sacc;
    if (lane == 16) sh2[warp] = sacc;
    __syncthreads();
    if (threadIdx.x == 0) {
        float t1 = 0.f, t2 = 0.f;
        #pragma unroll
        for (int w = 0; w < NWARP; w++) { t1 += sh1[w]; t2 += sh2[w]; }
        atomicAdd(&g_sum[0], (double)t1);
        atomicAdd(&g_sum[1], (double)t2);
    }
}

// Fused tail: scale out1/out2 AND momentum row update (was two kernels).
__global__ __launch_bounds__(256)
void finish_kernel(const float* __restrict__ v1, const float* __restrict__ v2,
                   const int* __restrict__ y,
                   const float* __restrict__ m1, const float* __restrict__ m2,
                   float* __restrict__ out1,      // base of out1 (out2 contiguous)
                   float* __restrict__ o_m1, float* __restrict__ o_m2,
                   int B, int K1, float factor_base)
{
    const int tid  = threadIdx.x;
    const int lane = tid & 31;
    const int warp = tid >> 5;

    const float inv1 = factor_base / (float)g_sum[0];
    const float inv2 = factor_base / (float)g_sum[1];

    // scale both out arrays (contiguous span; B*K1 divisible by 4)
    {
        const long total4    = ((long)2 * B * K1) >> 2;
        const long boundary4 = ((long)B * K1) >> 2;
        float4* o = reinterpret_cast<float4*>(out1);
        for (long i = (long)blockIdx.x * blockDim.x + tid; i < total4;
             i += (long)gridDim.x * blockDim.x) {
            float4 v = o[i];
            const float f = (i < boundary4) ? inv1 : inv2;
            v.x *= f; v.y *= f; v.z *= f; v.w *= f;
            o[i] = v;
        }
    }

    // momentum update + l2-normalize for the B touched rows (one warp each;
    // runs after main's copy in stream order, so these writes win).
    if (blockIdx.x < (unsigned)B && warp == 0) {
        const int bb  = blockIdx.x;
        const int row = y[bb];
        {
            float4 mv = reinterpret_cast<const float4*>(m1 + (long)row * D_DIM)[lane];
            float4 vv = reinterpret_cast<const float4*>(v1 + (long)bb * D_DIM)[lane];
            float4 u;
            u.x = MOM * mv.x + (1.f - MOM) * vv.x;
            u.y = MOM * mv.y + (1.f - MOM) * vv.y;
            u.z = MOM * mv.z + (1.f - MOM) * vv.z;
            u.w = MOM * mv.w + (1.f - MOM) * vv.w;
            float n = u.x * u.x + u.y * u.y + u.z * u.z + u.w * u.w;
            #pragma unroll
            for (int o = 16; o > 0; o >>= 1) n += __shfl_xor_sync(0xFFFFFFFFu, n, o);
            const float invn = 1.f / sqrtf(n);
            u.x *= invn; u.y *= invn; u.z *= invn; u.w *= invn;
            reinterpret_cast<float4*>(o_m1 + (long)row * D_DIM)[lane] = u;
        }
        {
            float4 mv = reinterpret_cast<const float4*>(m2 + (long)row * D_DIM)[lane];
            float4 vv = reinterpret_cast<const float4*>(v2 + (long)bb * D_DIM)[lane];
            float4 u;
            u.x = MOM * mv.x + (1.f - MOM) * vv.x;
            u.y = MOM * mv.y + (1.f - MOM) * vv.y;
            u.z = MOM * mv.z + (1.f - MOM) * vv.z;
            u.w = MOM * mv.w + (1.f - MOM) * vv.w;
            float n = u.x * u.x + u.y * u.y + u.z * u.z + u.w * u.w;
            #pragma unroll
            for (int o = 16; o > 0; o >>= 1) n += __shfl_xor_sync(0xFFFFFFFFu, n, o);
            const float invn = 1.f / sqrtf(n);
            u.x *= invn; u.y *= invn; u.z *= invn; u.w *= invn;
            reinterpret_cast<float4*>(o_m2 + (long)row * D_DIM)[lane] = u;
        }
    }
}

extern "C" void kernel_launch(void* const* d_in, const int* in_sizes, int n_in,
                              void* d_out, int out_size)
{
    const float* v1  = (const float*)d_in[0];
    const float* v2  = (const float*)d_in[1];
    const int*   idx = (const int*)d_in[2];
    const int*   y   = (const int*)d_in[3];
    const float* m1  = (const float*)d_in[4];
    const float* m2  = (const float*)d_in[5];

    const int  B  = in_sizes[3];               // 128
    const int  K1 = in_sizes[2] / B;           // 4097
    const long ND = in_sizes[4];               // N * D
    const int  N  = (int)(ND / D_DIM);         // 100000

    float* out  = (float*)d_out;
    float* out1 = out;                         // [B*K1]
    float* out2 = out + (long)B * K1;          // [B*K1]
    float* o_m1 = out + 2L * B * K1;           // [N*D]
    float* o_m2 = o_m1 + ND;                   // [N*D]

    init_sums_kernel<<<1, 32>>>();

    // dot blocks: B*SPLIT = 4096; copy blocks: 1024 (interleaved 1-in-5)
    const int nblocks = (B * SPLIT / 4) * 5;   // 5120
    main_kernel<<<nblocks, 256>>>(v1, v2, idx, m1, m2, out1, out2,
                                  o_m1, o_m2, K1, ND / 4);

    const float factor_base = (float)((double)((long)B * K1) / (double)N);
    finish_kernel<<<1024, 256>>>(v1, v2, y, m1, m2, out1, o_m1, o_m2,
                                 B, K1, factor_base);
}